// round 6
// baseline (speedup 1.0000x reference)
#include <cuda_runtime.h>
#include <cuda_fp16.h>
#include <math.h>
#include <stdint.h>

#define Nn 8192
#define Mm 2048
#define Dd 768
#define EPS_D 0.0025
#define L2E 1.4426950408889634f
#define LN2 0.6931471805599453
#define SCL (400.0f * L2E)   // cost scale in log2 units
#define NBLK 148

static __device__ float g_X[(size_t)Nn * Dd];
static __device__ float g_Y[(size_t)Mm * Dd];
static __device__ __align__(16) __half g_H[(size_t)Nn * Mm];   // (SC - off_i)*L2E
static __device__ __align__(16) __half g_HT[(size_t)Mm * Nn];
static __device__ float g_nx[Nn], g_ny[Mm], g_off[Nn];          // off in ln units
static __device__ float g_la[Nn], g_lb[Mm];                     // ln units
static __device__ float g_la2[Nn], g_lb2[Mm];                   // log2 units
static __device__ __align__(16) __half g_wah[Nn];               // wa2 (log2) fp16
static __device__ __align__(16) __half g_vbh[Mm];               // vb2 (log2) fp16
static __device__ float g_L2f[Nn], g_Lg2[Mm];                   // log2-LSE outputs
static __device__ float g_nybar;
static __device__ unsigned g_barc;
static __device__ unsigned g_barg;

__device__ __forceinline__ uint32_t tf32r(float x) {
    uint32_t u; asm("cvt.rna.tf32.f32 %0, %1;" : "=r"(u) : "f"(x)); return u;
}
__device__ __forceinline__ __half2 hexp2_(__half2 x) {
    uint32_t xi = *reinterpret_cast<uint32_t*>(&x), yi;
    asm("ex2.approx.f16x2 %0, %1;" : "=r"(yi) : "r"(xi));
    return *reinterpret_cast<__half2*>(&yi);
}

__global__ void prep_kernel(const float* __restrict__ h, const float* __restrict__ hi) {
    int i = blockIdx.x * blockDim.x + threadIdx.x;
    if (i < Nn) { float l = logf(h[i]); g_la[i] = l; g_la2[i] = l * L2E; }
    if (i < Mm) {
        float l = logf(hi[i]);
        g_lb[i] = l; g_lb2[i] = l * L2E;
        g_vbh[i] = __float2half(l * L2E);
    }
    if (i == 0) { g_barc = 0u; }
}

// ============ proj GEMM (tf32): Fout[rows, 768] = A @ W^T, tile 128x64 ============
__global__ void __launch_bounds__(256) proj_gemm(const float* __restrict__ A,
                                                 const float* __restrict__ B,
                                                 float* __restrict__ Fout) {
    __shared__ uint32_t As[128][36];
    __shared__ uint32_t Bs[64][36];
    const int t = threadIdx.x, lane = t & 31, wid = t >> 5;
    const int wm = wid & 1, wn = wid >> 1;
    const int bi = blockIdx.y * 128, bj = blockIdx.x * 64;
    const int ar = t >> 3, ac = (t & 7) * 4;

    float acc[4][2][4] = {};
    float4 pa[4], pb[2];
    #pragma unroll
    for (int p = 0; p < 4; p++) pa[p] = *(const float4*)(A + (size_t)(bi + ar + 32 * p) * Dd + ac);
    #pragma unroll
    for (int p = 0; p < 2; p++) pb[p] = *(const float4*)(B + (size_t)(bj + ar + 32 * p) * Dd + ac);

    const int tg = lane & 3, gp = lane >> 2;
    for (int ch = 0; ch < 24; ch++) {
        #pragma unroll
        for (int p = 0; p < 4; p++)
            *(uint4*)&As[ar + 32 * p][ac] = make_uint4(tf32r(pa[p].x), tf32r(pa[p].y), tf32r(pa[p].z), tf32r(pa[p].w));
        #pragma unroll
        for (int p = 0; p < 2; p++)
            *(uint4*)&Bs[ar + 32 * p][ac] = make_uint4(tf32r(pb[p].x), tf32r(pb[p].y), tf32r(pb[p].z), tf32r(pb[p].w));
        __syncthreads();
        if (ch < 23) {
            const int k0 = (ch + 1) * 32;
            #pragma unroll
            for (int p = 0; p < 4; p++) pa[p] = *(const float4*)(A + (size_t)(bi + ar + 32 * p) * Dd + k0 + ac);
            #pragma unroll
            for (int p = 0; p < 2; p++) pb[p] = *(const float4*)(B + (size_t)(bj + ar + 32 * p) * Dd + k0 + ac);
        }
        #pragma unroll
        for (int kk = 0; kk < 4; kk++) {
            uint32_t ua[4][4], ub[2][2];
            const int kc = kk * 8 + tg;
            #pragma unroll
            for (int im = 0; im < 4; im++) {
                const int rA = wm * 64 + im * 16 + gp;
                ua[im][0] = As[rA][kc];     ua[im][1] = As[rA + 8][kc];
                ua[im][2] = As[rA][kc + 4]; ua[im][3] = As[rA + 8][kc + 4];
            }
            #pragma unroll
            for (int jn = 0; jn < 2; jn++) {
                const int rB = wn * 16 + jn * 8 + gp;
                ub[jn][0] = Bs[rB][kc]; ub[jn][1] = Bs[rB][kc + 4];
            }
            #pragma unroll
            for (int im = 0; im < 4; im++)
                #pragma unroll
                for (int jn = 0; jn < 2; jn++)
                    asm volatile(
                        "mma.sync.aligned.m16n8k8.row.col.f32.tf32.tf32.f32 "
                        "{%0,%1,%2,%3}, {%4,%5,%6,%7}, {%8,%9}, {%0,%1,%2,%3};"
                        : "+f"(acc[im][jn][0]), "+f"(acc[im][jn][1]),
                          "+f"(acc[im][jn][2]), "+f"(acc[im][jn][3])
                        : "r"(ua[im][0]), "r"(ua[im][1]), "r"(ua[im][2]), "r"(ua[im][3]),
                          "r"(ub[jn][0]), "r"(ub[jn][1]));
        }
        __syncthreads();
    }
    #pragma unroll
    for (int im = 0; im < 4; im++) {
        const int r0 = bi + wm * 64 + im * 16 + gp;
        #pragma unroll
        for (int jn = 0; jn < 2; jn++) {
            const int cb = bj + wn * 16 + jn * 8 + 2 * tg;
            *(float2*)(Fout + (size_t)r0 * Dd + cb) = make_float2(acc[im][jn][0], acc[im][jn][1]);
            *(float2*)(Fout + (size_t)(r0 + 8) * Dd + cb) = make_float2(acc[im][jn][2], acc[im][jn][3]);
        }
    }
}

// ============ gram GEMM (tf32), tile 128x128, fused cost epilogue -> H and HT ============
__global__ void __launch_bounds__(256) gram_gemm(const float* __restrict__ A,
                                                 const float* __restrict__ B) {
    __shared__ union SU {
        struct { uint32_t As[128][36]; uint32_t Bs[128][36]; } k;
        __half tile[128][136];
    } su;
    const int t = threadIdx.x, lane = t & 31, wid = t >> 5;
    const int wm = wid & 1, wn = wid >> 1;       // wm: 2x64 rows, wn: 4x32 cols
    const int bi = blockIdx.y * 128, bj = blockIdx.x * 128;
    const int ar = t >> 1, ac = (t & 1) * 16;

    float acc[4][4][4] = {};
    const float* Ap = A + (size_t)(bi + ar) * Dd;
    const float* Bp = B + (size_t)(bj + ar) * Dd;
    float4 pa[4], pb[4];
    #pragma unroll
    for (int p = 0; p < 4; p++) {
        pa[p] = *(const float4*)(Ap + ac + 4 * p);
        pb[p] = *(const float4*)(Bp + ac + 4 * p);
    }
    const int tg = lane & 3, gp = lane >> 2;
    for (int ch = 0; ch < 24; ch++) {
        #pragma unroll
        for (int p = 0; p < 4; p++) {
            *(uint4*)&su.k.As[ar][ac + 4 * p] = make_uint4(tf32r(pa[p].x), tf32r(pa[p].y), tf32r(pa[p].z), tf32r(pa[p].w));
            *(uint4*)&su.k.Bs[ar][ac + 4 * p] = make_uint4(tf32r(pb[p].x), tf32r(pb[p].y), tf32r(pb[p].z), tf32r(pb[p].w));
        }
        __syncthreads();
        if (ch < 23) {
            const int k0 = (ch + 1) * 32;
            #pragma unroll
            for (int p = 0; p < 4; p++) {
                pa[p] = *(const float4*)(Ap + k0 + ac + 4 * p);
                pb[p] = *(const float4*)(Bp + k0 + ac + 4 * p);
            }
        }
        #pragma unroll
        for (int kk = 0; kk < 4; kk++) {
            uint32_t ua[4][4], ub[4][2];
            const int kc = kk * 8 + tg;
            #pragma unroll
            for (int im = 0; im < 4; im++) {
                const int rA = wm * 64 + im * 16 + gp;
                ua[im][0] = su.k.As[rA][kc];     ua[im][1] = su.k.As[rA + 8][kc];
                ua[im][2] = su.k.As[rA][kc + 4]; ua[im][3] = su.k.As[rA + 8][kc + 4];
            }
            #pragma unroll
            for (int jn = 0; jn < 4; jn++) {
                const int rB = wn * 32 + jn * 8 + gp;
                ub[jn][0] = su.k.Bs[rB][kc]; ub[jn][1] = su.k.Bs[rB][kc + 4];
            }
            #pragma unroll
            for (int im = 0; im < 4; im++)
                #pragma unroll
                for (int jn = 0; jn < 4; jn++)
                    asm volatile(
                        "mma.sync.aligned.m16n8k8.row.col.f32.tf32.tf32.f32 "
                        "{%0,%1,%2,%3}, {%4,%5,%6,%7}, {%8,%9}, {%0,%1,%2,%3};"
                        : "+f"(acc[im][jn][0]), "+f"(acc[im][jn][1]),
                          "+f"(acc[im][jn][2]), "+f"(acc[im][jn][3])
                        : "r"(ua[im][0]), "r"(ua[im][1]), "r"(ua[im][2]), "r"(ua[im][3]),
                          "r"(ub[jn][0]), "r"(ub[jn][1]));
        }
        __syncthreads();
    }

    const float nyb = g_nybar;
    __half2 hv[4][4][2];
    #pragma unroll
    for (int im = 0; im < 4; im++) {
        const int rl = wm * 64 + im * 16 + gp;
        const float nx0 = g_nx[bi + rl], nx1 = g_nx[bi + rl + 8];
        const float o0 = SCL * (nx0 + nyb), o1 = SCL * (nx1 + nyb);
        #pragma unroll
        for (int jn = 0; jn < 4; jn++) {
            const int cl = wn * 32 + jn * 8 + 2 * tg;
            const float ny0 = g_ny[bj + cl], ny1 = g_ny[bj + cl + 1];
            float v00 = SCL * fmaxf(nx0 + ny0 - acc[im][jn][0], 0.f) - o0;
            float v01 = SCL * fmaxf(nx0 + ny1 - acc[im][jn][1], 0.f) - o0;
            float v10 = SCL * fmaxf(nx1 + ny0 - acc[im][jn][2], 0.f) - o1;
            float v11 = SCL * fmaxf(nx1 + ny1 - acc[im][jn][3], 0.f) - o1;
            hv[im][jn][0] = __floats2half2_rn(v00, v01);
            hv[im][jn][1] = __floats2half2_rn(v10, v11);
            *(__half2*)(g_H + (size_t)(bi + rl) * Mm + bj + cl) = hv[im][jn][0];
            *(__half2*)(g_H + (size_t)(bi + rl + 8) * Mm + bj + cl) = hv[im][jn][1];
        }
    }
    __syncthreads();   // smem k-buffers dead; reuse as transpose tile
    #pragma unroll
    for (int im = 0; im < 4; im++) {
        const int rl = wm * 64 + im * 16 + gp;
        #pragma unroll
        for (int jn = 0; jn < 4; jn++) {
            const int cl = wn * 32 + jn * 8 + 2 * tg;
            su.tile[cl][rl]         = __low2half(hv[im][jn][0]);
            su.tile[cl + 1][rl]     = __high2half(hv[im][jn][0]);
            su.tile[cl][rl + 8]     = __low2half(hv[im][jn][1]);
            su.tile[cl + 1][rl + 8] = __high2half(hv[im][jn][1]);
        }
    }
    __syncthreads();
    const int c = t >> 1, rseg = (t & 1) * 64;
    const uint4* src = (const uint4*)&su.tile[c][rseg];
    uint4* dst = (uint4*)(g_HT + (size_t)(bj + c) * Nn + bi + rseg);
    #pragma unroll
    for (int q = 0; q < 8; q++) dst[q] = src[q];
}

// ============ warp-per-row squared norms for X and Y ============
__global__ void __launch_bounds__(256) rownorm2() {
    const int gwarp = blockIdx.x * 8 + (threadIdx.x >> 5);
    const int lane = threadIdx.x & 31;
    const float* X;
    float* outn;
    int row;
    if (gwarp < Nn) { X = g_X; outn = g_nx; row = gwarp; }
    else if (gwarp < Nn + Mm) { X = g_Y; outn = g_ny; row = gwarp - Nn; }
    else return;
    const float4* xr = (const float4*)(X + (size_t)row * Dd);
    float s = 0.f;
    #pragma unroll
    for (int k = 0; k < 6; k++) {
        float4 v = xr[lane + 32 * k];
        s = fmaf(v.x, v.x, s); s = fmaf(v.y, v.y, s);
        s = fmaf(v.z, v.z, s); s = fmaf(v.w, v.w, s);
    }
    #pragma unroll
    for (int o = 16; o > 0; o >>= 1) s += __shfl_xor_sync(0xffffffffu, s, o);
    if (lane == 0) outn[row] = 0.5f * s;
}

__global__ void nybar_kernel() {
    const int t = threadIdx.x;
    float s = 0.f;
    for (int j = t; j < Mm; j += 256) s += g_ny[j];
    __shared__ float sd[256];
    sd[t] = s; __syncthreads();
    for (int o = 128; o > 0; o >>= 1) { if (t < o) sd[t] += sd[t + o]; __syncthreads(); }
    if (t == 0) g_nybar = sd[0] / (float)Mm;
}

__global__ void off_kernel() {
    int i = blockIdx.x * blockDim.x + threadIdx.x;
    if (i < Nn) g_off[i] = 400.f * (g_nx[i] + g_nybar);
}

// ============ persistent Sinkhorn loop ============
__device__ __forceinline__ void gsync() {
    __syncthreads();
    __threadfence();
    if (threadIdx.x == 0) {
        unsigned gen = *(volatile unsigned*)&g_barg;
        if (atomicAdd(&g_barc, 1u) == NBLK - 1) {
            g_barc = 0;
            __threadfence();
            *(volatile unsigned*)&g_barg = gen + 1;
        } else {
            while (*(volatile unsigned*)&g_barg == gen) { __nanosleep(32); }
        }
        __threadfence();
    }
    __syncthreads();
}

__device__ __forceinline__ void rowA(int row, bool fin) {
    const int lane = threadIdx.x & 31;
    const uint4* Hr = (const uint4*)(g_H + (size_t)row * Mm);
    const uint4* Vr = (const uint4*)g_vbh;
    __half2 a[8][4];
    __half2 m2 = __float2half2_rn(-60000.f);
    #pragma unroll
    for (int q = 0; q < 8; q++) {
        const int idx = q * 32 + lane;
        uint4 hu = Hr[idx];
        uint4 vu = __ldcg(&Vr[idx]);
        const __half2* hp = (const __half2*)&hu;
        const __half2* vp = (const __half2*)&vu;
        #pragma unroll
        for (int c = 0; c < 4; c++) {
            a[q][c] = __hsub2(vp[c], hp[c]);
            m2 = __hmax2(m2, a[q][c]);
        }
    }
    float m = fmaxf(__half2float(__low2half(m2)), __half2float(__high2half(m2)));
    #pragma unroll
    for (int o = 16; o > 0; o >>= 1) m = fmaxf(m, __shfl_xor_sync(0xffffffffu, m, o));
    const __half2 mh = __float2half2_rn(m);
    float s0 = 0.f, s1 = 0.f;
    #pragma unroll
    for (int q = 0; q < 8; q++) {
        __half2 p = __float2half2_rn(0.f);
        #pragma unroll
        for (int c = 0; c < 4; c++) p = __hadd2(p, hexp2_(__hsub2(a[q][c], mh)));
        float pf = __half2float(__hadd(__low2half(p), __high2half(p)));
        if (q & 1) s1 += pf; else s0 += pf;
    }
    float s = s0 + s1;
    #pragma unroll
    for (int o = 16; o > 0; o >>= 1) s += __shfl_xor_sync(0xffffffffu, s, o);
    if (lane == 0) {
        float L = m + __log2f(s);
        if (fin) __stcg(&g_L2f[row], L);
        else __stcg((short*)&g_wah[row], (short)__half_as_ushort(__float2half(g_la2[row] - L)));
    }
}

__global__ void __launch_bounds__(512, 1) sink_loop(const float* __restrict__ h,
                                                    const float* __restrict__ hi,
                                                    float* __restrict__ out) {
    const int t = threadIdx.x, lane = t & 31, wid = t >> 5;
    const int gw = blockIdx.x * 16 + wid;
    __shared__ float sM[4][4], sS[4][4];

    for (int it = 0; it < 50; it++) {
        for (int row = gw; row < Nn; row += NBLK * 16) rowA(row, false);
        gsync();
        // phase B: 4 rows of HT per block pass, 4 warps per row
        for (int base = blockIdx.x * 4; base < Mm; base += NBLK * 4) {
            const int rl = wid >> 2, quarter = wid & 3;
            const int row = base + rl;
            const uint4* Hr = (const uint4*)(g_HT + (size_t)row * Nn);
            const uint4* Vr = (const uint4*)g_wah;
            __half2 a[8][4];
            __half2 m2 = __float2half2_rn(-60000.f);
            #pragma unroll
            for (int q = 0; q < 8; q++) {
                const int idx = quarter * 256 + q * 32 + lane;
                uint4 hu = Hr[idx];
                uint4 vu = __ldcg(&Vr[idx]);
                const __half2* hp = (const __half2*)&hu;
                const __half2* vp = (const __half2*)&vu;
                #pragma unroll
                for (int c = 0; c < 4; c++) {
                    a[q][c] = __hsub2(vp[c], hp[c]);
                    m2 = __hmax2(m2, a[q][c]);
                }
            }
            float m = fmaxf(__half2float(__low2half(m2)), __half2float(__high2half(m2)));
            #pragma unroll
            for (int o = 16; o > 0; o >>= 1) m = fmaxf(m, __shfl_xor_sync(0xffffffffu, m, o));
            const __half2 mh = __float2half2_rn(m);
            float s0 = 0.f, s1 = 0.f;
            #pragma unroll
            for (int q = 0; q < 8; q++) {
                __half2 p = __float2half2_rn(0.f);
                #pragma unroll
                for (int c = 0; c < 4; c++) p = __hadd2(p, hexp2_(__hsub2(a[q][c], mh)));
                float pf = __half2float(__hadd(__low2half(p), __high2half(p)));
                if (q & 1) s1 += pf; else s0 += pf;
            }
            float s = s0 + s1;
            #pragma unroll
            for (int o = 16; o > 0; o >>= 1) s += __shfl_xor_sync(0xffffffffu, s, o);
            if (lane == 0) { sM[rl][quarter] = m; sS[rl][quarter] = s; }
            __syncthreads();
            if (t < 4) {
                float M2 = sM[t][0];
                #pragma unroll
                for (int w = 1; w < 4; w++) M2 = fmaxf(M2, sM[t][w]);
                float S2 = 0.f;
                #pragma unroll
                for (int w = 0; w < 4; w++) S2 += sS[t][w] * exp2f(sM[t][w] - M2);
                float L = M2 + __log2f(S2);
                const int r = base + t;
                __stcg((short*)&g_vbh[r], (short)__half_as_ushort(__float2half(g_lb2[r] - L)));
                __stcg(&g_Lg2[r], L);
            }
            __syncthreads();
        }
        gsync();
    }
    // final differentiable f extrapolation
    for (int row = gw; row < Nn; row += NBLK * 16) rowA(row, true);
    gsync();

    if (blockIdx.x == 0) {
        double acc = 0.0;
        for (int i = t; i < Nn; i += 512)
            acc += (double)h[i] * (LN2 * (double)__ldcg(&g_L2f[i]) - (double)g_off[i] - 0.5 * (double)g_la[i]);
        for (int j = t; j < Mm; j += 512)
            acc += (double)hi[j] * (LN2 * (double)__ldcg(&g_Lg2[j]) - 0.5 * (double)g_lb[j]);
        __shared__ double sd[512];
        sd[t] = acc; __syncthreads();
        for (int o = 256; o > 0; o >>= 1) { if (t < o) sd[t] += sd[t + o]; __syncthreads(); }
        if (t == 0) out[0] = (float)exp(EPS_D * sd[0]);
    }
}

extern "C" void kernel_launch(void* const* d_in, const int* in_sizes, int n_in,
                              void* d_out, int out_size) {
    const float *dp = nullptr, *sip = nullptr, *hp = nullptr, *hip = nullptr, *Wp = nullptr;
    for (int i = 0; i < n_in; i++) {
        switch (in_sizes[i]) {
            case Nn * Dd: dp  = (const float*)d_in[i]; break;
            case Mm * Dd: sip = (const float*)d_in[i]; break;
            case Nn:      hp  = (const float*)d_in[i]; break;
            case Mm:      hip = (const float*)d_in[i]; break;
            case Dd * Dd: Wp  = (const float*)d_in[i]; break;
        }
    }
    if (!dp)  dp  = (const float*)d_in[0];
    if (!sip) sip = (const float*)d_in[1];
    if (!hp)  hp  = (const float*)d_in[2];
    if (!hip) hip = (const float*)d_in[3];
    if (!Wp)  Wp  = (const float*)d_in[4];

    float* gX; cudaGetSymbolAddress((void**)&gX, g_X);
    float* gY; cudaGetSymbolAddress((void**)&gY, g_Y);

    prep_kernel<<<(Nn + 255) / 256, 256>>>(hp, hip);
    proj_gemm<<<dim3(Dd / 64, Nn / 128), 256>>>(dp, Wp, gX);
    proj_gemm<<<dim3(Dd / 64, Mm / 128), 256>>>(sip, Wp, gY);
    rownorm2<<<(Nn + Mm) / 8, 256>>>();
    nybar_kernel<<<1, 256>>>();
    off_kernel<<<(Nn + 255) / 256, 256>>>();
    gram_gemm<<<dim3(Mm / 128, Nn / 128), 256>>>(gX, gY);
    sink_loop<<<NBLK, 512>>>(hp, hip, (float*)d_out);
}

// round 7
// speedup vs baseline: 1.8604x; 1.8604x over previous
#include <cuda_runtime.h>
#include <cuda_fp16.h>
#include <math.h>
#include <stdint.h>

#define Nn 8192
#define Mm 2048
#define Dd 768
#define EPS_D 0.0025
#define L2E 1.4426950408889634f
#define LN2 0.6931471805599453
#define SCL (400.0f * L2E)   // cost scale in log2 units

static __device__ __align__(16) __half g_dh[(size_t)Nn * Dd];
static __device__ __align__(16) __half g_sih[(size_t)Mm * Dd];
static __device__ __align__(16) __half g_Wh[(size_t)Dd * Dd];
static __device__ __align__(16) __half g_Xh[(size_t)Nn * Dd];
static __device__ __align__(16) __half g_Yh[(size_t)Mm * Dd];
static __device__ __align__(16) __half g_H[(size_t)Nn * Mm];   // (SC - off_i)*L2E
static __device__ __align__(16) __half g_HT[(size_t)Mm * Nn];
static __device__ float g_nx[Nn], g_ny[Mm], g_off[Nn];          // off in ln units
static __device__ float g_la[Nn], g_lb[Mm];                     // ln units
static __device__ float g_la2[Nn], g_lb2[Mm];                   // log2 units
static __device__ __align__(16) __half g_wah[Nn];               // wa2 (log2) fp16
static __device__ __align__(16) __half g_vbh[Mm];               // vb2 (log2) fp16
static __device__ float g_L2f[Nn], g_Lg2[Mm];                   // log2-LSE outputs
static __device__ float g_nybar;

__device__ __forceinline__ __half2 hexp2_(__half2 x) {
    uint32_t xi = *reinterpret_cast<uint32_t*>(&x), yi;
    asm("ex2.approx.f16x2 %0, %1;" : "=r"(yi) : "r"(xi));
    return *reinterpret_cast<__half2*>(&yi);
}
__device__ __forceinline__ uint32_t packh2(float a, float b) {
    __half2 h = __floats2half2_rn(a, b);
    return *reinterpret_cast<uint32_t*>(&h);
}

__global__ void prep_kernel(const float* __restrict__ h, const float* __restrict__ hi) {
    int i = blockIdx.x * blockDim.x + threadIdx.x;
    if (i < Nn) { float l = logf(h[i]); g_la[i] = l; g_la2[i] = l * L2E; }
    if (i < Mm) {
        float l = logf(hi[i]);
        g_lb[i] = l; g_lb2[i] = l * L2E;
        g_vbh[i] = __float2half(l * L2E);
    }
}

// fp32 -> fp16 conversion of d, si, W (float4 granularity)
#define D4 (Nn * Dd / 4)
#define S4 (Mm * Dd / 4)
#define W4 (Dd * Dd / 4)
__global__ void conv_kernel(const float* __restrict__ dp, const float* __restrict__ sip,
                            const float* __restrict__ Wp) {
    int idx = blockIdx.x * blockDim.x + threadIdx.x;
    const float* src; __half* dst; int q;
    if (idx < D4) { src = dp; dst = g_dh; q = idx; }
    else if (idx < D4 + S4) { src = sip; dst = g_sih; q = idx - D4; }
    else if (idx < D4 + S4 + W4) { src = Wp; dst = g_Wh; q = idx - D4 - S4; }
    else return;
    float4 v = ((const float4*)src)[q];
    ((uint2*)dst)[q] = make_uint2(packh2(v.x, v.y), packh2(v.z, v.w));
}

// ============ fp16 GEMM: C = A[ma,768] @ B[nb,768]^T, tile 128x128, 256 thr ============
// EPI=0: write half C (ld=ldc).  EPI=1: cost epilogue -> g_H and g_HT.
template <int EPI>
__global__ void __launch_bounds__(256) h_gemm(const __half* __restrict__ A,
                                              const __half* __restrict__ B,
                                              __half* __restrict__ Cout, int ldc) {
    __shared__ union SU {
        struct { __half As[128][72]; __half Bs[128][72]; } k;
        __half tile[128][136];
    } su;
    const int t = threadIdx.x, lane = t & 31, wid = t >> 5;
    const int wm = wid & 1, wn = wid >> 1;        // wm: 2x64 rows, wn: 4x32 cols
    const int bi = blockIdx.y * 128, bj = blockIdx.x * 128;
    const int ar = t >> 1, side = (t & 1) * 32;   // 2 threads per row, 32 halves each
    const int tg = lane & 3, gp = lane >> 2;

    float acc[4][4][4] = {};
    const uint4* Ap = (const uint4*)(A + (size_t)(bi + ar) * Dd + side);
    const uint4* Bp = (const uint4*)(B + (size_t)(bj + ar) * Dd + side);
    uint4 pa[4], pb[4];
    #pragma unroll
    for (int q = 0; q < 4; q++) { pa[q] = Ap[q]; pb[q] = Bp[q]; }

    for (int ch = 0; ch < 12; ch++) {
        #pragma unroll
        for (int q = 0; q < 4; q++) {
            *(uint4*)&su.k.As[ar][side + 8 * q] = pa[q];
            *(uint4*)&su.k.Bs[ar][side + 8 * q] = pb[q];
        }
        __syncthreads();
        if (ch < 11) {
            const int o = (ch + 1) * 8;   // 64 halves = 8 uint4
            #pragma unroll
            for (int q = 0; q < 4; q++) { pa[q] = Ap[o + q]; pb[q] = Bp[o + q]; }
        }
        #pragma unroll
        for (int kk = 0; kk < 4; kk++) {
            const int kc = kk * 16;
            uint32_t ua[4][4], ub[4][2];
            #pragma unroll
            for (int im = 0; im < 4; im++) {
                const int rA = wm * 64 + im * 16 + gp;
                ua[im][0] = *(const uint32_t*)&su.k.As[rA][kc + 2 * tg];
                ua[im][1] = *(const uint32_t*)&su.k.As[rA + 8][kc + 2 * tg];
                ua[im][2] = *(const uint32_t*)&su.k.As[rA][kc + 8 + 2 * tg];
                ua[im][3] = *(const uint32_t*)&su.k.As[rA + 8][kc + 8 + 2 * tg];
            }
            #pragma unroll
            for (int jn = 0; jn < 4; jn++) {
                const int rB = wn * 32 + jn * 8 + gp;
                ub[jn][0] = *(const uint32_t*)&su.k.Bs[rB][kc + 2 * tg];
                ub[jn][1] = *(const uint32_t*)&su.k.Bs[rB][kc + 8 + 2 * tg];
            }
            #pragma unroll
            for (int im = 0; im < 4; im++)
                #pragma unroll
                for (int jn = 0; jn < 4; jn++)
                    asm volatile(
                        "mma.sync.aligned.m16n8k16.row.col.f32.f16.f16.f32 "
                        "{%0,%1,%2,%3}, {%4,%5,%6,%7}, {%8,%9}, {%0,%1,%2,%3};"
                        : "+f"(acc[im][jn][0]), "+f"(acc[im][jn][1]),
                          "+f"(acc[im][jn][2]), "+f"(acc[im][jn][3])
                        : "r"(ua[im][0]), "r"(ua[im][1]), "r"(ua[im][2]), "r"(ua[im][3]),
                          "r"(ub[jn][0]), "r"(ub[jn][1]));
        }
        __syncthreads();
    }

    if (EPI == 0) {
        #pragma unroll
        for (int im = 0; im < 4; im++) {
            const int r0 = bi + wm * 64 + im * 16 + gp;
            #pragma unroll
            for (int jn = 0; jn < 4; jn++) {
                const int cb = bj + wn * 32 + jn * 8 + 2 * tg;
                *(uint32_t*)&Cout[(size_t)r0 * ldc + cb] = packh2(acc[im][jn][0], acc[im][jn][1]);
                *(uint32_t*)&Cout[(size_t)(r0 + 8) * ldc + cb] = packh2(acc[im][jn][2], acc[im][jn][3]);
            }
        }
    } else {
        const float nyb = g_nybar;
        __half2 hv[4][4][2];
        #pragma unroll
        for (int im = 0; im < 4; im++) {
            const int rl = wm * 64 + im * 16 + gp;
            const float nx0 = g_nx[bi + rl], nx1 = g_nx[bi + rl + 8];
            const float o0 = SCL * (nx0 + nyb), o1 = SCL * (nx1 + nyb);
            #pragma unroll
            for (int jn = 0; jn < 4; jn++) {
                const int cl = wn * 32 + jn * 8 + 2 * tg;
                const float ny0 = g_ny[bj + cl], ny1 = g_ny[bj + cl + 1];
                float v00 = SCL * fmaxf(nx0 + ny0 - acc[im][jn][0], 0.f) - o0;
                float v01 = SCL * fmaxf(nx0 + ny1 - acc[im][jn][1], 0.f) - o0;
                float v10 = SCL * fmaxf(nx1 + ny0 - acc[im][jn][2], 0.f) - o1;
                float v11 = SCL * fmaxf(nx1 + ny1 - acc[im][jn][3], 0.f) - o1;
                hv[im][jn][0] = __floats2half2_rn(v00, v01);
                hv[im][jn][1] = __floats2half2_rn(v10, v11);
                *(__half2*)(g_H + (size_t)(bi + rl) * Mm + bj + cl) = hv[im][jn][0];
                *(__half2*)(g_H + (size_t)(bi + rl + 8) * Mm + bj + cl) = hv[im][jn][1];
            }
        }
        __syncthreads();   // k-buffers dead; reuse smem as transpose tile
        #pragma unroll
        for (int im = 0; im < 4; im++) {
            const int rl = wm * 64 + im * 16 + gp;
            #pragma unroll
            for (int jn = 0; jn < 4; jn++) {
                const int cl = wn * 32 + jn * 8 + 2 * tg;
                su.tile[cl][rl]         = __low2half(hv[im][jn][0]);
                su.tile[cl + 1][rl]     = __high2half(hv[im][jn][0]);
                su.tile[cl][rl + 8]     = __low2half(hv[im][jn][1]);
                su.tile[cl + 1][rl + 8] = __high2half(hv[im][jn][1]);
            }
        }
        __syncthreads();
        const int c = t >> 1, rseg = (t & 1) * 64;
        const uint4* src = (const uint4*)&su.tile[c][rseg];
        uint4* dst = (uint4*)(g_HT + (size_t)(bj + c) * Nn + bi + rseg);
        #pragma unroll
        for (int q = 0; q < 8; q++) dst[q] = src[q];
    }
}

// ============ warp-per-row squared norms (reads fp16 X/Y) ============
__global__ void __launch_bounds__(256) rownorm2() {
    const int gwarp = blockIdx.x * 8 + (threadIdx.x >> 5);
    const int lane = threadIdx.x & 31;
    const __half* X;
    float* outn;
    int row;
    if (gwarp < Nn) { X = g_Xh; outn = g_nx; row = gwarp; }
    else if (gwarp < Nn + Mm) { X = g_Yh; outn = g_ny; row = gwarp - Nn; }
    else return;
    const uint4* xr = (const uint4*)(X + (size_t)row * Dd);
    float s = 0.f;
    #pragma unroll
    for (int k = 0; k < 3; k++) {
        uint4 u = xr[lane + 32 * k];
        const __half2* hp = (const __half2*)&u;
        #pragma unroll
        for (int c = 0; c < 4; c++) {
            float2 f = __half22float2(hp[c]);
            s = fmaf(f.x, f.x, s); s = fmaf(f.y, f.y, s);
        }
    }
    #pragma unroll
    for (int o = 16; o > 0; o >>= 1) s += __shfl_xor_sync(0xffffffffu, s, o);
    if (lane == 0) outn[row] = 0.5f * s;
}

__global__ void nybar_kernel() {
    const int t = threadIdx.x;
    float s = 0.f;
    for (int j = t; j < Mm; j += 256) s += g_ny[j];
    __shared__ float sd[256];
    sd[t] = s; __syncthreads();
    for (int o = 128; o > 0; o >>= 1) { if (t < o) sd[t] += sd[t + o]; __syncthreads(); }
    if (t == 0) g_nybar = sd[0] / (float)Mm;
}

__global__ void off_kernel() {
    int i = blockIdx.x * blockDim.x + threadIdx.x;
    if (i < Nn) g_off[i] = 400.f * (g_nx[i] + g_nybar);
}

// ============ two-pass half2 softmin over H rows (2048 cols, 1 warp/row) ============
template <int FINAL>
__global__ void __launch_bounds__(256) softminA() {
    const int t = threadIdx.x, lane = t & 31, wid = t >> 5;
    const int row = blockIdx.x * 8 + wid;
    const uint4* Hr = (const uint4*)(g_H + (size_t)row * Mm);
    const uint4* Vr = (const uint4*)g_vbh;

    __half2 a[8][4];
    __half2 m2 = __float2half2_rn(-60000.f);
    #pragma unroll
    for (int q = 0; q < 8; q++) {
        const int idx = q * 32 + lane;
        uint4 hu = Hr[idx];
        uint4 vu = __ldg(&Vr[idx]);
        const __half2* hp = (const __half2*)&hu;
        const __half2* vp = (const __half2*)&vu;
        #pragma unroll
        for (int c = 0; c < 4; c++) {
            a[q][c] = __hsub2(vp[c], hp[c]);
            m2 = __hmax2(m2, a[q][c]);
        }
    }
    float m = fmaxf(__half2float(__low2half(m2)), __half2float(__high2half(m2)));
    #pragma unroll
    for (int o = 16; o > 0; o >>= 1) m = fmaxf(m, __shfl_xor_sync(0xffffffffu, m, o));
    const __half2 mh = __float2half2_rn(m);

    float s0 = 0.f, s1 = 0.f;
    #pragma unroll
    for (int q = 0; q < 8; q++) {
        __half2 p = __float2half2_rn(0.f);
        #pragma unroll
        for (int c = 0; c < 4; c++) p = __hadd2(p, hexp2_(__hsub2(a[q][c], mh)));
        float pf = __half2float(__hadd(__low2half(p), __high2half(p)));
        if (q & 1) s1 += pf; else s0 += pf;
    }
    float s = s0 + s1;
    #pragma unroll
    for (int o = 16; o > 0; o >>= 1) s += __shfl_xor_sync(0xffffffffu, s, o);
    if (lane == 0) {
        float L = m + __log2f(s);
        if (FINAL) g_L2f[row] = L;
        else g_wah[row] = __float2half(g_la2[row] - L);
    }
}

// ============ softmin over HT rows (8192 cols, 4 warps/row, 2 rows/block) ============
__global__ void __launch_bounds__(256) softminB() {
    const int t = threadIdx.x, lane = t & 31, wid = t >> 5;
    const int rloc = wid >> 2, quarter = wid & 3;
    const int row = blockIdx.x * 2 + rloc;
    const uint4* Hr = (const uint4*)(g_HT + (size_t)row * Nn);
    const uint4* Vr = (const uint4*)g_wah;

    __half2 a[8][4];
    __half2 m2 = __float2half2_rn(-60000.f);
    #pragma unroll
    for (int q = 0; q < 8; q++) {
        const int idx = quarter * 256 + q * 32 + lane;
        uint4 hu = Hr[idx];
        uint4 vu = __ldg(&Vr[idx]);
        const __half2* hp = (const __half2*)&hu;
        const __half2* vp = (const __half2*)&vu;
        #pragma unroll
        for (int c = 0; c < 4; c++) {
            a[q][c] = __hsub2(vp[c], hp[c]);
            m2 = __hmax2(m2, a[q][c]);
        }
    }
    float m = fmaxf(__half2float(__low2half(m2)), __half2float(__high2half(m2)));
    #pragma unroll
    for (int o = 16; o > 0; o >>= 1) m = fmaxf(m, __shfl_xor_sync(0xffffffffu, m, o));
    const __half2 mh = __float2half2_rn(m);

    float s0 = 0.f, s1 = 0.f;
    #pragma unroll
    for (int q = 0; q < 8; q++) {
        __half2 p = __float2half2_rn(0.f);
        #pragma unroll
        for (int c = 0; c < 4; c++) p = __hadd2(p, hexp2_(__hsub2(a[q][c], mh)));
        float pf = __half2float(__hadd(__low2half(p), __high2half(p)));
        if (q & 1) s1 += pf; else s0 += pf;
    }
    float s = s0 + s1;
    #pragma unroll
    for (int o = 16; o > 0; o >>= 1) s += __shfl_xor_sync(0xffffffffu, s, o);

    __shared__ float sM[2][4], sS[2][4];
    if (lane == 0) { sM[rloc][quarter] = m; sS[rloc][quarter] = s; }
    __syncthreads();
    if (t < 2) {
        float M2 = sM[t][0];
        #pragma unroll
        for (int w = 1; w < 4; w++) M2 = fmaxf(M2, sM[t][w]);
        float S2 = 0.f;
        #pragma unroll
        for (int w = 0; w < 4; w++) S2 += sS[t][w] * exp2f(sM[t][w] - M2);
        float L = M2 + __log2f(S2);
        const int r = blockIdx.x * 2 + t;
        g_vbh[r] = __float2half(g_lb2[r] - L);
        g_Lg2[r] = L;
    }
}

__global__ void final_kernel(const float* __restrict__ h, const float* __restrict__ hi,
                             float* __restrict__ out) {
    const int t = threadIdx.x;
    double acc = 0.0;
    for (int i = t; i < Nn; i += 256)
        acc += (double)h[i] * (LN2 * (double)g_L2f[i] - (double)g_off[i] - 0.5 * (double)g_la[i]);
    for (int j = t; j < Mm; j += 256)
        acc += (double)hi[j] * (LN2 * (double)g_Lg2[j] - 0.5 * (double)g_lb[j]);
    __shared__ double sd[256];
    sd[t] = acc; __syncthreads();
    for (int o = 128; o > 0; o >>= 1) { if (t < o) sd[t] += sd[t + o]; __syncthreads(); }
    if (t == 0) out[0] = (float)exp(EPS_D * sd[0]);
}

extern "C" void kernel_launch(void* const* d_in, const int* in_sizes, int n_in,
                              void* d_out, int out_size) {
    const float *dp = nullptr, *sip = nullptr, *hp = nullptr, *hip = nullptr, *Wp = nullptr;
    for (int i = 0; i < n_in; i++) {
        switch (in_sizes[i]) {
            case Nn * Dd: dp  = (const float*)d_in[i]; break;
            case Mm * Dd: sip = (const float*)d_in[i]; break;
            case Nn:      hp  = (const float*)d_in[i]; break;
            case Mm:      hip = (const float*)d_in[i]; break;
            case Dd * Dd: Wp  = (const float*)d_in[i]; break;
        }
    }
    if (!dp)  dp  = (const float*)d_in[0];
    if (!sip) sip = (const float*)d_in[1];
    if (!hp)  hp  = (const float*)d_in[2];
    if (!hip) hip = (const float*)d_in[3];
    if (!Wp)  Wp  = (const float*)d_in[4];

    __half* gXh; cudaGetSymbolAddress((void**)&gXh, g_Xh);
    __half* gYh; cudaGetSymbolAddress((void**)&gYh, g_Yh);
    __half* gdh; cudaGetSymbolAddress((void**)&gdh, g_dh);
    __half* gsih; cudaGetSymbolAddress((void**)&gsih, g_sih);
    __half* gWh; cudaGetSymbolAddress((void**)&gWh, g_Wh);

    prep_kernel<<<(Nn + 255) / 256, 256>>>(hp, hip);
    conv_kernel<<<(D4 + S4 + W4 + 255) / 256, 256>>>(dp, sip, Wp);
    h_gemm<0><<<dim3(Dd / 128, Nn / 128), 256>>>(gdh, gWh, gXh, Dd);
    h_gemm<0><<<dim3(Dd / 128, Mm / 128), 256>>>(gsih, gWh, gYh, Dd);
    rownorm2<<<(Nn + Mm) / 8, 256>>>();
    nybar_kernel<<<1, 256>>>();
    off_kernel<<<(Nn + 255) / 256, 256>>>();
    h_gemm<1><<<dim3(Mm / 128, Nn / 128), 256>>>(gXh, gYh, nullptr, 0);

    for (int it = 0; it < 50; it++) {
        softminA<0><<<Nn / 8, 256>>>();
        softminB<<<Mm / 2, 256>>>();
    }
    softminA<1><<<Nn / 8, 256>>>();

    final_kernel<<<1, 256>>>(hp, hip, (float*)d_out);
}